// round 11
// baseline (speedup 1.0000x reference)
#include <cuda_runtime.h>
#include <cstdint>
#include <cstddef>

#define TT  8
#define NN  10000
#define FIN 128
#define HD  64
#define EE  160000
#define G4  (4*HD)          // 256 gate rows

// ---------------- scratch (static device globals; no allocation) -------------
__device__ float g_xw  [TT*NN*HD];        // x @ W_gcn            (20.5 MB)
__device__ float g_dinv[TT*NN];           // deg -> 1/sqrt(deg)   (0.3 MB)
__device__ float g_agg [TT*NN*HD];        // scattered GCN output (20.5 MB)
__device__ float g_gin [TT*G4*NN];        // input gates, TRANSPOSED [t][row][n]

// ---------------- helpers -----------------------------------------------------
__device__ __forceinline__ unsigned long long fma2(unsigned long long a,
                                                   unsigned long long b,
                                                   unsigned long long c) {
    unsigned long long d;
    asm("fma.rn.f32x2 %0, %1, %2, %3;" : "=l"(d) : "l"(a), "l"(b), "l"(c));
    return d;
}
__device__ __forceinline__ unsigned long long add2(unsigned long long a,
                                                   unsigned long long b) {
    unsigned long long d;
    asm("add.rn.f32x2 %0, %1, %2;" : "=l"(d) : "l"(a), "l"(b));
    return d;
}
__device__ __forceinline__ unsigned long long pack2(float lo, float hi) {
    unsigned long long p;
    asm("mov.b64 %0, {%1, %2};" : "=l"(p) : "f"(lo), "f"(hi));
    return p;
}
__device__ __forceinline__ float2 unpack2(unsigned long long p) {
    float lo, hi;
    asm("mov.b64 {%0, %1}, %2;" : "=f"(lo), "=f"(hi) : "l"(p));
    return make_float2(lo, hi);
}
__device__ __forceinline__ int clampN(int v) {
    return v < 0 ? 0 : (v >= NN ? NN - 1 : v);
}

// ---------------- GCN phase ---------------------------------------------------
// edge_index is int32 (JAX x64-disabled downcasts jnp.int64 -> int32).

__global__ void count_kernel(const int* __restrict__ ei) {
    int idx = blockIdx.x * 256 + threadIdx.x;
    if (idx >= TT * EE) return;
    int t = idx / EE;
    int e = idx - t * EE;
    int dst = clampN(ei[(size_t)t * 2 * EE + EE + e]);
    atomicAdd(&g_dinv[t * NN + dst], 1.0f);
}

__global__ void dinv_kernel() {
    int i = blockIdx.x * 256 + threadIdx.x;
    if (i >= TT * NN) return;
    g_dinv[i] = rsqrtf(1.0f + g_dinv[i]);
}

// xw = x @ W_gcn : 8 rows / block, W in smem
__global__ void xw_kernel(const float* __restrict__ x, const float* __restrict__ Wg) {
    __shared__ float Ws[FIN * HD];   // 32 KB
    __shared__ float xs[8][FIN];     // 4 KB
    int tid  = threadIdx.x;          // 512 threads
    int row0 = blockIdx.x * 8;
    for (int i = tid; i < FIN * HD; i += 512) Ws[i] = Wg[i];
    for (int i = tid; i < 8 * FIN;  i += 512)
        xs[i >> 7][i & 127] = x[(size_t)(row0 + (i >> 7)) * FIN + (i & 127)];
    __syncthreads();
    int r = tid >> 6, j = tid & 63;
    float acc = 0.0f;
#pragma unroll 16
    for (int k = 0; k < FIN; k++) acc = fmaf(xs[r][k], Ws[k * HD + j], acc);
    g_xw[(size_t)(row0 + r) * HD + j] = acc;
}

// scatter: agg[dst] += xw[src] * dinv[src]*dinv[dst], vectorized red.v4
__global__ void scatter_kernel(const int* __restrict__ ei) {
    int idx = blockIdx.x * 256 + threadIdx.x;        // T*E*16 threads
    int eg  = idx >> 4;
    int c   = idx & 15;
    int t   = eg / EE;
    int e   = eg - t * EE;
    int src = clampN(ei[(size_t)t * 2 * EE + e]);
    int dst = clampN(ei[(size_t)t * 2 * EE + EE + e]);
    float norm = g_dinv[t * NN + src] * g_dinv[t * NN + dst];
    const float4 v = *(const float4*)&g_xw[((size_t)t * NN + src) * HD + c * 4];
    float4 s = make_float4(v.x * norm, v.y * norm, v.z * norm, v.w * norm);
    float* p = &g_agg[((size_t)t * NN + dst) * HD + c * 4];
    asm volatile("red.global.add.v4.f32 [%0], {%1,%2,%3,%4};"
                 :: "l"(p), "f"(s.x), "f"(s.y), "f"(s.z), "f"(s.w) : "memory");
}

// gin = relu(agg + self_loop + b_gcn) @ W_ih^T + (b_ih + b_hh)
// 32 (t,n)-rows per block; OUTPUT IS TRANSPOSED: g_gin[t][gate_row][n].
__global__ void gin_kernel(const float* __restrict__ Wih, const float* __restrict__ bgcn,
                           const float* __restrict__ bih, const float* __restrict__ bhh) {
    __shared__ float as[32][HD];      // 8 KB
    __shared__ float sg[G4][33];      // 33 KB, padded (conflict-free transpose)
    int tid  = threadIdx.x;           // 256 threads
    int row0 = blockIdx.x * 32;       // global (t,n) row base
    for (int i = tid; i < 32 * HD; i += 256) {
        int r = i >> 6, k = i & 63;
        int rg = row0 + r;
        float dv = g_dinv[rg];
        float v = g_agg[(size_t)rg * HD + k] + g_xw[(size_t)rg * HD + k] * dv * dv + bgcn[k];
        as[r][k] = fmaxf(v, 0.0f);
    }
    __syncthreads();
    int j = tid;                      // gate row 0..255
    float w[HD];
    const float4* wp = (const float4*)(Wih + (size_t)j * HD);
#pragma unroll
    for (int q = 0; q < 16; q++) {
        float4 v = __ldg(wp + q);
        w[4*q] = v.x; w[4*q+1] = v.y; w[4*q+2] = v.z; w[4*q+3] = v.w;
    }
    float bias = bih[j] + bhh[j];
#pragma unroll 4
    for (int r = 0; r < 32; r++) {
        float a_ = bias;
        const float4* av = (const float4*)&as[r][0];
#pragma unroll
        for (int q = 0; q < 16; q++) {
            float4 h4 = av[q];
            a_ = fmaf(h4.x, w[4*q],   a_);
            a_ = fmaf(h4.y, w[4*q+1], a_);
            a_ = fmaf(h4.z, w[4*q+2], a_);
            a_ = fmaf(h4.w, w[4*q+3], a_);
        }
        sg[j][r] = a_;
    }
    __syncthreads();
    int wix  = tid >> 5;
    int lane = tid & 31;
    int rg   = row0 + lane;
    int tt_  = rg / NN;
    int nn_  = rg - tt_ * NN;
#pragma unroll 4
    for (int jj = 0; jj < 32; jj++) {
        int jr = wix * 32 + jj;
        g_gin[((size_t)tt_ * G4 + jr) * NN + nn_] = sg[jr][lane];
    }
}

// ---------------- LSTM scan: 4 warps (1/SMSP), 2 gate-rows per thread ---------
// 128 threads. Pair p = tid>>1 owns hidden unit u=p (same warp: lanes 2u,2u+1).
//   even thread: rows u (i-gate) and 128+u (g-gate)
//   odd  thread: rows 64+u (f)    and 192+u (o)
// h LDS amortized over both rows; gate exchange via 2x shfl_xor(1);
// c,h computed redundantly in both threads (no divergent branch);
// even thread stores h (smem + out) under predication.
__global__ void __launch_bounds__(128, 1)
lstm_kernel(const float* __restrict__ Whh, float* __restrict__ out) {
    __shared__ __align__(16) float hbuf[2][HD];

    int t    = blockIdx.x;
    int tid  = threadIdx.x;          // 128
    int odd  = tid & 1;
    int u    = tid >> 1;             // hidden unit 0..63
    int rowa = odd * 64 + u;         // i (even) / f (odd)
    int rowb = 128 + odd * 64 + u;   // g (even) / o (odd)

    // activation constants: row a is always sigmoid; row b: tanh (even) / sigmoid (odd)
    float am_b = odd ? 1.0f : 2.0f;
    float aa_b = odd ? 1.0f : 2.0f;
    float ab_b = odd ? 0.0f : -1.0f;

    // two W_hh rows pinned in registers as f32x2
    unsigned long long wa[32], wb[32];
    {
        const ulonglong2* pa = (const ulonglong2*)(Whh + (size_t)rowa * HD);
        const ulonglong2* pb = (const ulonglong2*)(Whh + (size_t)rowb * HD);
#pragma unroll
        for (int q = 0; q < 16; q++) {
            ulonglong2 va = __ldg(pa + q);
            ulonglong2 vb = __ldg(pb + q);
            wa[2*q] = va.x; wa[2*q+1] = va.y;
            wb[2*q] = vb.x; wb[2*q+1] = vb.y;
        }
    }

    if (tid < HD) hbuf[0][tid] = 0.0f;
    __syncthreads();

    float c = 0.0f;
    const float* gpa = g_gin + ((size_t)t * G4 + rowa) * NN;
    const float* gpb = g_gin + ((size_t)t * G4 + rowb) * NN;
    float* op = out + (size_t)t * NN * HD + u;

    float4 cura = __ldg((const float4*)gpa);
    float4 curb = __ldg((const float4*)gpb);
    float4 nxta = cura, nxtb = curb;

    for (int n0 = 0; n0 < NN; n0 += 4) {
        if (n0 + 4 < NN) {
            nxta = __ldg((const float4*)(gpa + n0 + 4));
            nxtb = __ldg((const float4*)(gpb + n0 + 4));
        }

#pragma unroll
        for (int s = 0; s < 4; s++) {
            int n = n0 + s;
            int b = s & 1;
            float gina = (s == 0) ? cura.x : (s == 1) ? cura.y : (s == 2) ? cura.z : cura.w;
            float ginb = (s == 0) ? curb.x : (s == 1) ? curb.y : (s == 2) ? curb.z : curb.w;

            // two dots sharing the h loads; 2 chains per row, depth 16
            unsigned long long a0 = pack2(gina, 0.0f), a1 = 0ull;
            unsigned long long b0 = pack2(ginb, 0.0f), b1 = 0ull;
            const ulonglong2* hv = (const ulonglong2*)&hbuf[b][0];
#pragma unroll
            for (int q = 0; q < 16; q++) {
                ulonglong2 p = hv[q];
                a0 = fma2(p.x, wa[2*q],     a0);
                a1 = fma2(p.y, wa[2*q + 1], a1);
                b0 = fma2(p.x, wb[2*q],     b0);
                b1 = fma2(p.y, wb[2*q + 1], b1);
            }
            float2 fa = unpack2(add2(a0, a1));
            float2 fb = unpack2(add2(b0, b1));
            float acc_a = fa.x + fa.y;
            float acc_b = fb.x + fb.y;

            // activations (row a: sigmoid; row b: tanh/sigmoid per parity)
            float ua = __expf(-acc_a);
            float act_a = __fdividef(1.0f, 1.0f + ua);                  // i or f
            float ub = __expf(-am_b * acc_b);
            float act_b = fmaf(aa_b, __fdividef(1.0f, 1.0f + ub), ab_b); // g or o

            // pair exchange: even(i,g) <-> odd(f,o)
            float x1 = __shfl_xor_sync(0xffffffffu, act_a, 1);
            float x2 = __shfl_xor_sync(0xffffffffu, act_b, 1);
            float i_ = odd ? x1    : act_a;
            float f_ = odd ? act_a : x1;
            float g_ = odd ? x2    : act_b;
            float o_ = odd ? act_b : x2;

            // redundant c,h in both threads of the pair
            c = fmaf(f_, c, i_ * g_);
            float e2 = __expf(-2.0f * c);
            float th = fmaf(2.0f, __fdividef(1.0f, 1.0f + e2), -1.0f);
            float h_ = o_ * th;

            if (!odd) {                      // short predicated arm
                op[(size_t)n * HD] = h_;
                hbuf[b ^ 1][u] = h_;
            }
            __syncthreads();
        }
        cura = nxta;
        curb = nxtb;
    }
}

// ---------------- launch ------------------------------------------------------
extern "C" void kernel_launch(void* const* d_in, const int* in_sizes, int n_in,
                              void* d_out, int out_size) {
    const float* x    = (const float*)d_in[0];
    const int*   ei   = (const int*)d_in[1];     // int32
    const float* Wg   = (const float*)d_in[2];
    const float* bg   = (const float*)d_in[3];
    const float* Wih  = (const float*)d_in[4];
    const float* Whh  = (const float*)d_in[5];
    const float* bih  = (const float*)d_in[6];
    const float* bhh  = (const float*)d_in[7];
    float*       out  = (float*)d_out;

    void *p_dinv, *p_agg;
    cudaGetSymbolAddress(&p_dinv, g_dinv);
    cudaGetSymbolAddress(&p_agg,  g_agg);
    cudaMemsetAsync(p_dinv, 0, sizeof(float) * TT * NN, 0);
    cudaMemsetAsync(p_agg,  0, sizeof(float) * (size_t)TT * NN * HD, 0);

    count_kernel  <<<(TT * EE + 255) / 256, 256>>>(ei);
    dinv_kernel   <<<(TT * NN + 255) / 256, 256>>>();
    xw_kernel     <<<TT * NN / 8, 512>>>(x, Wg);
    scatter_kernel<<<(TT * EE * 16) / 256, 256>>>(ei);
    gin_kernel    <<<TT * NN / 32, 256>>>(Wih, bg, bih, bhh);
    lstm_kernel   <<<TT, 128>>>(Whh, out);
}